// round 6
// baseline (speedup 1.0000x reference)
#include <cuda_runtime.h>
#include <math.h>

#define G 64
#define G3 262144
#define BATCH 4
#define NPTS 200000
#define NVOX (BATCH*G3)

// ------------------------- device scratch (no allocs allowed) -------------------------
static __device__ float    g_vox[NVOX];                    // histogram volume
static __device__ float    g_samp[NVOX];                   // grid-sampled volume
static __device__ float    g_y[(size_t)NVOX * 64];         // pre-BN conv1 output, channel-last
static __device__ unsigned g_mm[BATCH * 6];                // encoded min[3], max[3]
static __device__ double   g_stats[128];                   // sum[64], sumsq[64] (branch 1)
static __device__ double   g_stats2[128];                  // (branch 2)
static __device__ float    g_ab[128];                      // BN affine a[64], b[64]
static __device__ float    g_ab2[128];

// ------------------------- helpers -------------------------
__device__ __forceinline__ unsigned fenc(float f) {
    unsigned u = __float_as_uint(f);
    return u ^ ((unsigned)((int)u >> 31) | 0x80000000u);
}
__device__ __forceinline__ float fdec(unsigned e) {
    unsigned mask = ((int)e < 0) ? 0x80000000u : 0xFFFFFFFFu;
    return __uint_as_float(e ^ mask);
}
// div.full.f32: XLA-GPU's lowering of f32 divide (-nvptx-prec-divf32=1).
__device__ __forceinline__ float div_full(float a, float b) {
    float r;
    asm("div.full.f32 %0, %1, %2;" : "=f"(r) : "f"(a), "f"(b));
    return r;
}

// ------------------------- init -------------------------
__global__ void init_kernel() {
    int i = blockIdx.x * blockDim.x + threadIdx.x;
    int stride = gridDim.x * blockDim.x;
    for (int v = i; v < NVOX; v += stride) g_vox[v] = 0.0f;
    if (i < 128) { g_stats[i] = 0.0; g_stats2[i] = 0.0; }
    if (i < BATCH * 6) g_mm[i] = ((i % 6) < 3) ? 0xFFFFFFFFu : 0u;
}

// ------------------------- per-batch min/max -------------------------
__global__ void minmax_kernel(const float* __restrict__ pts) {
    int b = blockIdx.y;
    const float* p = pts + (size_t)b * NPTS * 3;
    float mn[3] = {1e30f, 1e30f, 1e30f};
    float mx[3] = {-1e30f, -1e30f, -1e30f};
    for (int i = blockIdx.x * blockDim.x + threadIdx.x; i < NPTS; i += gridDim.x * blockDim.x) {
#pragma unroll
        for (int k = 0; k < 3; k++) {
            float v = p[(size_t)i * 3 + k];
            mn[k] = fminf(mn[k], v);
            mx[k] = fmaxf(mx[k], v);
        }
    }
#pragma unroll
    for (int o = 16; o > 0; o >>= 1) {
#pragma unroll
        for (int k = 0; k < 3; k++) {
            mn[k] = fminf(mn[k], __shfl_xor_sync(0xffffffffu, mn[k], o));
            mx[k] = fmaxf(mx[k], __shfl_xor_sync(0xffffffffu, mx[k], o));
        }
    }
    if ((threadIdx.x & 31) == 0) {
#pragma unroll
        for (int k = 0; k < 3; k++) {
            atomicMin(&g_mm[b * 6 + k], fenc(mn[k]));
            atomicMax(&g_mm[b * 6 + 3 + k], fenc(mx[k]));
        }
    }
}

// ------------------------- histogram voxelization -------------------------
// bin = floor(64 * div.full(p-mn, mx-mn+1e-6)); the +-*0.5 chain is exactly
// equivalent to t*64 in fp32 (proved: Sterbenz + exact power-of-2 scaling),
// so the division flavor is the only free variable vs the XLA reference.
__global__ void hist_kernel(const float* __restrict__ pts) {
    int t = blockIdx.x * blockDim.x + threadIdx.x;
    if (t >= BATCH * NPTS) return;
    int b = t / NPTS;
    int i = t - b * NPTS;
    const float* p = pts + ((size_t)b * NPTS + i) * 3;
    int id[3];
#pragma unroll
    for (int k = 0; k < 3; k++) {
        float mn = fdec(g_mm[b * 6 + k]);
        float mx = fdec(g_mm[b * 6 + 3 + k]);
        float num = __fsub_rn(p[k], mn);
        float den = __fadd_rn(__fsub_rn(mx, mn), 1e-6f);
        float t0  = div_full(num, den);
        float u   = t0 * (float)G;          // exact (power-of-2 scale)
        int ii = (int)floorf(u);
        id[k] = min(max(ii, 0), G - 1);
    }
    int lin = (id[0] * G + id[1]) * G + id[2];
    atomicAdd(&g_vox[b * G3 + lin], 1.0f);
}

// ------------------------- conv3d 1->64 (SAME), pre-BN y channel-last -------------------------
// block 128 threads, tile 8x8x8 voxels, 4 voxels/thread along x
__global__ __launch_bounds__(128) void conv1_kernel(int src, const float* __restrict__ wg,
                                                    const float* __restrict__ bias) {
    __shared__ float sin_s[10][10][10];
    __shared__ float ws[64 * 27];
    __shared__ float bs[64];
    const float* in = src ? g_samp : g_vox;
    int tid = threadIdx.x;
    int b = blockIdx.z >> 3;
    int z0 = (blockIdx.z & 7) * 8;
    int y0 = blockIdx.y * 8, x0 = blockIdx.x * 8;
    const float* inb = in + (size_t)b * G3;

    for (int i = tid; i < 1000; i += 128) {
        int lz = i / 100, r = i - lz * 100, ly = r / 10, lx = r - ly * 10;
        int gz = z0 + lz - 1, gy = y0 + ly - 1, gx = x0 + lx - 1;
        float v = 0.0f;
        if ((unsigned)gz < G && (unsigned)gy < G && (unsigned)gx < G)
            v = inb[(gz * G + gy) * G + gx];
        sin_s[lz][ly][lx] = v;
    }
    for (int i = tid; i < 1728; i += 128) ws[i] = wg[i];
    if (tid < 64) bs[tid] = bias[tid];
    __syncthreads();

    int xg = tid & 1, y = (tid >> 1) & 7, z = tid >> 4;
    size_t voxbase = (size_t)(b * G3 + ((z0 + z) * G + (y0 + y)) * G + x0 + xg * 4);

#pragma unroll 1
    for (int c0 = 0; c0 < 64; c0 += 16) {
        float acc[4][16];
#pragma unroll
        for (int vx = 0; vx < 4; vx++)
#pragma unroll
            for (int c = 0; c < 16; c++) acc[vx][c] = bs[c0 + c];

#pragma unroll 1
        for (int dz = 0; dz < 3; dz++) {
#pragma unroll
            for (int dy = 0; dy < 3; dy++) {
                float v[6];
#pragma unroll
                for (int j = 0; j < 6; j++) v[j] = sin_s[z + dz][y + dy][xg * 4 + j];
#pragma unroll
                for (int dx = 0; dx < 3; dx++) {
#pragma unroll
                    for (int c = 0; c < 16; c++) {
                        float wv = ws[(c0 + c) * 27 + (dz * 3 + dy) * 3 + dx];
#pragma unroll
                        for (int vx = 0; vx < 4; vx++)
                            acc[vx][c] = fmaf(wv, v[vx + dx], acc[vx][c]);
                    }
                }
            }
        }
#pragma unroll
        for (int vx = 0; vx < 4; vx++) {
            float* dst = g_y + (voxbase + vx) * 64 + c0;
#pragma unroll
            for (int c4 = 0; c4 < 4; c4++) {
                float4 o = make_float4(acc[vx][c4 * 4 + 0], acc[vx][c4 * 4 + 1],
                                       acc[vx][c4 * 4 + 2], acc[vx][c4 * 4 + 3]);
                *(float4*)(dst + c4 * 4) = o;
            }
        }
    }
}

// ------------------------- per-channel sum / sumsq -------------------------
__global__ __launch_bounds__(256) void stats_kernel(int which) {
    __shared__ double red[256][8];
    double* st = which ? g_stats2 : g_stats;
    int tid = threadIdx.x;
    int g = tid & 15;   // channel quad
    int r = tid >> 4;   // voxel row within block
    double s0 = 0, s1 = 0, s2 = 0, s3 = 0, q0 = 0, q1 = 0, q2 = 0, q3 = 0;
    for (int v = blockIdx.x * 16 + r; v < NVOX; v += gridDim.x * 16) {
        float4 y4 = *(const float4*)(g_y + (size_t)v * 64 + g * 4);
        s0 += y4.x; q0 += (double)y4.x * (double)y4.x;
        s1 += y4.y; q1 += (double)y4.y * (double)y4.y;
        s2 += y4.z; q2 += (double)y4.z * (double)y4.z;
        s3 += y4.w; q3 += (double)y4.w * (double)y4.w;
    }
    red[tid][0] = s0; red[tid][1] = s1; red[tid][2] = s2; red[tid][3] = s3;
    red[tid][4] = q0; red[tid][5] = q1; red[tid][6] = q2; red[tid][7] = q3;
    __syncthreads();
    for (int stp = 8; stp; stp >>= 1) {
        if (r < stp) {
#pragma unroll
            for (int j = 0; j < 8; j++) red[tid][j] += red[tid + stp * 16][j];
        }
        __syncthreads();
    }
    if (r == 0) {
#pragma unroll
        for (int k = 0; k < 4; k++) {
            atomicAdd(&st[g * 4 + k], red[tid][k]);
            atomicAdd(&st[64 + g * 4 + k], red[tid][4 + k]);
        }
    }
}

// ------------------------- BN affine finalize -------------------------
__global__ void finalize_kernel(int which, const float* __restrict__ gamma,
                                const float* __restrict__ beta) {
    int c = threadIdx.x;
    const double* st = which ? g_stats2 : g_stats;
    float* ab = which ? g_ab2 : g_ab;
    if (c < 64) {
        double mean = st[c] * (1.0 / (double)NVOX);
        double var = st[64 + c] * (1.0 / (double)NVOX) - mean * mean;
        float a = gamma[c] * (float)(1.0 / sqrt(var + 1e-5));
        ab[c] = a;
        ab[64 + c] = beta[c] - (float)mean * a;
    }
}

// ------------------------- conv3d 64->OC, fused BN+ReLU on loads -------------------------
// EPI=0: OC=3 offset conv + meshgrid + clip + trilinear border sample -> g_samp
// EPI=1: OC=1 conv + sigmoid -> outp
// block 128 threads, tile 8x4x4 output voxels; channel-split 2x32; XOR swizzled smem.
template <int OC, int EPI>
__global__ __launch_bounds__(128) void conv2_kernel(const float* __restrict__ wg,
                                                    const float* __restrict__ bias, int which,
                                                    float* __restrict__ outp) {
    extern __shared__ float sh[];
    float* hs = sh;                    // 360 positions * 32 channels (swizzled quads)
    float* ws = sh + 11520;            // OC * 27 * 32
    float* sab = ws + OC * 864;        // 128
    const float* ab = which ? g_ab2 : g_ab;

    int tid = threadIdx.x;
    int b = blockIdx.z >> 4;
    int z0 = (blockIdx.z & 15) * 4;
    int y0 = blockIdx.y * 4, x0 = blockIdx.x * 8;
    int tx = tid & 7, ty = (tid >> 3) & 3, tz = tid >> 5;

    if (tid < 128) sab[tid] = ab[tid];

    float accv[OC];
#pragma unroll
    for (int oc = 0; oc < OC; oc++) accv[oc] = 0.0f;

#pragma unroll 1
    for (int p = 0; p < 2; p++) {
        __syncthreads();
        for (int i = tid; i < OC * 864; i += 128) {
            int oc = i / 864, rr = i - oc * 864, tap = rr >> 5, ic = rr & 31;
            ws[i] = wg[(oc * 64 + p * 32 + ic) * 27 + tap];
        }
        for (int i = tid; i < 2880; i += 128) {
            int c4 = i & 7, pos = i >> 3;
            int lz = pos / 60, rem = pos - lz * 60, ly = rem / 10, lx = rem - ly * 10;
            int gz = z0 + lz - 1, gy = y0 + ly - 1, gx = x0 + lx - 1;
            float4 v = make_float4(0.f, 0.f, 0.f, 0.f);
            if ((unsigned)gz < G && (unsigned)gy < G && (unsigned)gx < G) {
                float4 yv = *(const float4*)(g_y + ((size_t)(b * G3 + (gz * G + gy) * G + gx)) * 64 +
                                             p * 32 + c4 * 4);
                float4 a4 = *(const float4*)(sab + p * 32 + c4 * 4);
                float4 b4 = *(const float4*)(sab + 64 + p * 32 + c4 * 4);
                v.x = fmaxf(fmaf(a4.x, yv.x, b4.x), 0.f);
                v.y = fmaxf(fmaf(a4.y, yv.y, b4.y), 0.f);
                v.z = fmaxf(fmaf(a4.z, yv.z, b4.z), 0.f);
                v.w = fmaxf(fmaf(a4.w, yv.w, b4.w), 0.f);
            }
            *(float4*)&hs[(size_t)(pos * 8 + (c4 ^ (pos & 7))) * 4] = v;
        }
        __syncthreads();

#pragma unroll 1
        for (int dz = 0; dz < 3; dz++) {
#pragma unroll
            for (int dy = 0; dy < 3; dy++) {
#pragma unroll
                for (int dx = 0; dx < 3; dx++) {
                    int pos = ((tz + dz) * 6 + (ty + dy)) * 10 + (tx + dx);
                    int tap = (dz * 3 + dy) * 3 + dx;
                    int sw = pos & 7;
                    const float* hp = hs + pos * 32;
                    const float* wp = ws + tap * 32;
#pragma unroll
                    for (int c4 = 0; c4 < 8; c4++) {
                        float4 v = *(const float4*)(hp + ((c4 ^ sw) * 4));
#pragma unroll
                        for (int oc = 0; oc < OC; oc++) {
                            float4 w4 = *(const float4*)(wp + oc * 864 + c4 * 4);
                            accv[oc] += v.x * w4.x + v.y * w4.y + v.z * w4.z + v.w * w4.w;
                        }
                    }
                }
            }
        }
    }

    int d = z0 + tz, hh = y0 + ty, wxx = x0 + tx;
    int vlin = (d * G + hh) * G + wxx;

    if constexpr (EPI == 0) {
        const float step = 2.0f / 63.0f;
        float o0 = accv[0] + bias[0];
        float o1 = accv[1] + bias[1];
        float o2 = accv[2] + bias[2];
        // grid ch0 -> x (W) coord, ch1 -> y (H), ch2 -> z (D); base = (lin[d], lin[h], lin[w])
        float gxc = fminf(fmaxf(-1.0f + d * step + 0.1f * o0, -1.0f), 1.0f);
        float gyc = fminf(fmaxf(-1.0f + hh * step + 0.1f * o1, -1.0f), 1.0f);
        float gzc = fminf(fmaxf(-1.0f + wxx * step + 0.1f * o2, -1.0f), 1.0f);
        float ux = fminf(fmaxf(((gxc + 1.0f) * (float)G - 1.0f) * 0.5f, 0.0f), (float)(G - 1));
        float uy = fminf(fmaxf(((gyc + 1.0f) * (float)G - 1.0f) * 0.5f, 0.0f), (float)(G - 1));
        float uz = fminf(fmaxf(((gzc + 1.0f) * (float)G - 1.0f) * 0.5f, 0.0f), (float)(G - 1));
        float fx0 = floorf(ux), fy0 = floorf(uy), fz0 = floorf(uz);
        float fx = ux - fx0, fy = uy - fy0, fz = uz - fz0;
        int x0i = (int)fx0, y0i = (int)fy0, z0i = (int)fz0;
        int x1i = min(x0i + 1, G - 1), y1i = min(y0i + 1, G - 1), z1i = min(z0i + 1, G - 1);
        const float* vb = g_vox + b * G3;
        float v000 = vb[(z0i * G + y0i) * G + x0i];
        float v001 = vb[(z0i * G + y0i) * G + x1i];
        float v010 = vb[(z0i * G + y1i) * G + x0i];
        float v011 = vb[(z0i * G + y1i) * G + x1i];
        float v100 = vb[(z1i * G + y0i) * G + x0i];
        float v101 = vb[(z1i * G + y0i) * G + x1i];
        float v110 = vb[(z1i * G + y1i) * G + x0i];
        float v111 = vb[(z1i * G + y1i) * G + x1i];
        float wx0 = 1.0f - fx, wy0 = 1.0f - fy, wz0 = 1.0f - fz;
        float r = wz0 * (wy0 * (v000 * wx0 + v001 * fx) + fy * (v010 * wx0 + v011 * fx)) +
                  fz  * (wy0 * (v100 * wx0 + v101 * fx) + fy * (v110 * wx0 + v111 * fx));
        g_samp[b * G3 + vlin] = r;
    } else {
        float o = accv[0] + bias[0];
        outp[b * G3 + vlin] = 1.0f / (1.0f + expf(-o));
    }
}

// ------------------------- launch -------------------------
extern "C" void kernel_launch(void* const* d_in, const int* in_sizes, int n_in,
                              void* d_out, int out_size) {
    const float* points = (const float*)d_in[0];
    const float* ow1 = (const float*)d_in[1];
    const float* ob1 = (const float*)d_in[2];
    const float* ogamma = (const float*)d_in[3];
    const float* obeta = (const float*)d_in[4];
    const float* ow2 = (const float*)d_in[5];
    const float* ob2 = (const float*)d_in[6];
    const float* dw1 = (const float*)d_in[7];
    const float* db1 = (const float*)d_in[8];
    const float* dgamma = (const float*)d_in[9];
    const float* dbeta = (const float*)d_in[10];
    const float* dw2 = (const float*)d_in[11];
    const float* db2 = (const float*)d_in[12];
    float* outp = (float*)d_out;

    static bool attr_done = false;
    if (!attr_done) {
        cudaFuncSetAttribute(conv2_kernel<3, 0>, cudaFuncAttributeMaxDynamicSharedMemorySize, 57344);
        cudaFuncSetAttribute(conv2_kernel<1, 1>, cudaFuncAttributeMaxDynamicSharedMemorySize, 51200);
        attr_done = true;
    }

    init_kernel<<<2048, 256>>>();
    minmax_kernel<<<dim3(64, BATCH), 256>>>(points);
    hist_kernel<<<(BATCH * NPTS + 255) / 256, 256>>>(points);

    // branch 1: offset conv + grid sample
    conv1_kernel<<<dim3(8, 8, BATCH * 8), 128>>>(0, ow1, ob1);
    stats_kernel<<<1024, 256>>>(0);
    finalize_kernel<<<1, 64>>>(0, ogamma, obeta);
    conv2_kernel<3, 0><<<dim3(8, 16, BATCH * 16), 128, 56960>>>(ow2, ob2, 0, nullptr);

    // branch 2: decoder
    conv1_kernel<<<dim3(8, 8, BATCH * 8), 128>>>(1, dw1, db1);
    stats_kernel<<<1024, 256>>>(1);
    finalize_kernel<<<1, 64>>>(1, dgamma, dbeta);
    conv2_kernel<1, 1><<<dim3(8, 16, BATCH * 16), 128, 50048>>>(dw2, db2, 1, outp);
}

// round 8
// speedup vs baseline: 1.7510x; 1.7510x over previous
#include <cuda_runtime.h>
#include <math.h>

#define G 64
#define G3 262144
#define BATCH 4
#define NPTS 200000
#define NVOX (BATCH*G3)
#define NBLK1 2048           // conv1 grid size (partial-stats rows)

typedef unsigned long long ull;

// ------------------------- device scratch (no allocs allowed) -------------------------
static __device__ float    g_vox[NVOX];                    // histogram volume
static __device__ float    g_samp[NVOX];                   // grid-sampled volume
static __device__ float    g_y[(size_t)NVOX * 64];         // pre-BN conv1 output, channel-last
static __device__ unsigned g_mm[BATCH * 6];                // encoded min[3], max[3]
static __device__ ull      g_psum[NBLK1 * 32];             // per-block packed channel-pair sums (32 pairs)
static __device__ ull      g_psq[NBLK1 * 32];              // per-block packed channel-pair sumsq
static __device__ float    g_ab[128];                      // BN affine a[64], b[64] (branch 1)
static __device__ float    g_ab2[128];                     // (branch 2)

// ------------------------- helpers -------------------------
__device__ __forceinline__ unsigned fenc(float f) {
    unsigned u = __float_as_uint(f);
    return u ^ ((unsigned)((int)u >> 31) | 0x80000000u);
}
__device__ __forceinline__ float fdec(unsigned e) {
    unsigned mask = ((int)e < 0) ? 0x80000000u : 0xFFFFFFFFu;
    return __uint_as_float(e ^ mask);
}
// div.full.f32: XLA-GPU's lowering of f32 divide (the correctness-critical op)
__device__ __forceinline__ float div_full(float a, float b) {
    float r;
    asm("div.full.f32 %0, %1, %2;" : "=f"(r) : "f"(a), "f"(b));
    return r;
}
// packed fp32x2 ops (two exact IEEE fp32 ops per instruction)
__device__ __forceinline__ void fma2(ull& d, ull a, ull b) {
    asm("fma.rn.f32x2 %0, %1, %2, %0;" : "+l"(d) : "l"(a), "l"(b));
}
__device__ __forceinline__ ull add2(ull a, ull b) {
    ull r;
    asm("add.rn.f32x2 %0, %1, %2;" : "=l"(r) : "l"(a), "l"(b));
    return r;
}
__device__ __forceinline__ ull pk(float lo, float hi) {
    ull r;
    asm("mov.b64 %0, {%1, %2};" : "=l"(r) : "f"(lo), "f"(hi));
    return r;
}
__device__ __forceinline__ float2 unpk(ull v) {
    float2 r;
    asm("mov.b64 {%0, %1}, %2;" : "=f"(r.x), "=f"(r.y) : "l"(v));
    return r;
}

// ------------------------- init -------------------------
__global__ void init_kernel() {
    int i = blockIdx.x * blockDim.x + threadIdx.x;
    int stride = gridDim.x * blockDim.x;
    for (int v = i; v < NVOX; v += stride) g_vox[v] = 0.0f;
    if (i < BATCH * 6) g_mm[i] = ((i % 6) < 3) ? 0xFFFFFFFFu : 0u;
}

// ------------------------- per-batch min/max -------------------------
__global__ void minmax_kernel(const float* __restrict__ pts) {
    int b = blockIdx.y;
    const float* p = pts + (size_t)b * NPTS * 3;
    float mn[3] = {1e30f, 1e30f, 1e30f};
    float mx[3] = {-1e30f, -1e30f, -1e30f};
    for (int i = blockIdx.x * blockDim.x + threadIdx.x; i < NPTS; i += gridDim.x * blockDim.x) {
#pragma unroll
        for (int k = 0; k < 3; k++) {
            float v = p[(size_t)i * 3 + k];
            mn[k] = fminf(mn[k], v);
            mx[k] = fmaxf(mx[k], v);
        }
    }
#pragma unroll
    for (int o = 16; o > 0; o >>= 1) {
#pragma unroll
        for (int k = 0; k < 3; k++) {
            mn[k] = fminf(mn[k], __shfl_xor_sync(0xffffffffu, mn[k], o));
            mx[k] = fmaxf(mx[k], __shfl_xor_sync(0xffffffffu, mx[k], o));
        }
    }
    if ((threadIdx.x & 31) == 0) {
#pragma unroll
        for (int k = 0; k < 3; k++) {
            atomicMin(&g_mm[b * 6 + k], fenc(mn[k]));
            atomicMax(&g_mm[b * 6 + 3 + k], fenc(mx[k]));
        }
    }
}

// ------------------------- histogram voxelization (do not touch: correctness-pinned) -------------------------
__global__ void hist_kernel(const float* __restrict__ pts) {
    int t = blockIdx.x * blockDim.x + threadIdx.x;
    if (t >= BATCH * NPTS) return;
    int b = t / NPTS;
    int i = t - b * NPTS;
    const float* p = pts + ((size_t)b * NPTS + i) * 3;
    int id[3];
#pragma unroll
    for (int k = 0; k < 3; k++) {
        float mn = fdec(g_mm[b * 6 + k]);
        float mx = fdec(g_mm[b * 6 + 3 + k]);
        float num = __fsub_rn(p[k], mn);
        float den = __fadd_rn(__fsub_rn(mx, mn), 1e-6f);
        float t0  = div_full(num, den);
        float u   = t0 * (float)G;          // exact (power-of-2 scale)
        int ii = (int)floorf(u);
        id[k] = min(max(ii, 0), G - 1);
    }
    int lin = (id[0] * G + id[1]) * G + id[2];
    atomicAdd(&g_vox[b * G3 + lin], 1.0f);
}

// ------------------------- conv3d 1->64 (SAME) + fused partial BN stats -------------------------
// channels-in-lanes: lane l owns channels {2l, 2l+1}; weights in registers (packed pairs).
// block 128 threads, tile 8x8x8 voxels; warp w handles z-slices {2w, 2w+1}, 4 x-voxels per group.
__global__ __launch_bounds__(128) void conv1_kernel(int src, const float* __restrict__ wg,
                                                    const float* __restrict__ bias) {
    __shared__ float sin_s[10][10][10];
    __shared__ ull swr[2][4][32];
    const float* in = src ? g_samp : g_vox;
    int tid = threadIdx.x;
    int lane = tid & 31, w = tid >> 5;
    int b = blockIdx.z >> 3;
    int z0 = (blockIdx.z & 7) * 8;
    int y0 = blockIdx.y * 8, x0 = blockIdx.x * 8;
    const float* inb = in + (size_t)b * G3;

    for (int i = tid; i < 1000; i += 128) {
        int lz = i / 100, r = i - lz * 100, ly = r / 10, lx = r - ly * 10;
        int gz = z0 + lz - 1, gy = y0 + ly - 1, gx = x0 + lx - 1;
        float v = 0.0f;
        if ((unsigned)gz < G && (unsigned)gy < G && (unsigned)gx < G)
            v = inb[(gz * G + gy) * G + gx];
        sin_s[lz][ly][lx] = v;
    }
    // per-lane weight pairs: 27 taps x channels (2l, 2l+1)
    ull w2[27];
#pragma unroll
    for (int t = 0; t < 27; t++)
        w2[t] = pk(wg[(2 * lane) * 27 + t], wg[(2 * lane + 1) * 27 + t]);
    ull b2 = pk(bias[2 * lane], bias[2 * lane + 1]);
    __syncthreads();

    ull sum2 = 0, sq2 = 0;
#pragma unroll 1
    for (int zz = 0; zz < 2; zz++) {
        int z = w * 2 + zz;
#pragma unroll 1
        for (int y = 0; y < 8; y++) {
#pragma unroll
            for (int xg = 0; xg < 2; xg++) {
                ull acc2[4] = {b2, b2, b2, b2};
#pragma unroll
                for (int dz = 0; dz < 3; dz++) {
#pragma unroll
                    for (int dy = 0; dy < 3; dy++) {
                        const float* row = &sin_s[z + dz][y + dy][xg * 4];
                        ull vv[6];
#pragma unroll
                        for (int j = 0; j < 6; j++) { float v = row[j]; vv[j] = pk(v, v); }
#pragma unroll
                        for (int dx = 0; dx < 3; dx++) {
                            ull wt = w2[(dz * 3 + dy) * 3 + dx];
#pragma unroll
                            for (int vx = 0; vx < 4; vx++) fma2(acc2[vx], wt, vv[dx + vx]);
                        }
                    }
                }
                size_t vox = (size_t)(b * G3 + ((z0 + z) * G + (y0 + y)) * G + x0 + xg * 4);
#pragma unroll
                for (int vx = 0; vx < 4; vx++) {
                    *(ull*)(g_y + (vox + vx) * 64 + 2 * lane) = acc2[vx];
                    sum2 = add2(sum2, acc2[vx]);
                    fma2(sq2, acc2[vx], acc2[vx]);
                }
            }
        }
    }
    // cross-warp reduce of packed channel-pair stats
    swr[0][w][lane] = sum2;
    swr[1][w][lane] = sq2;
    __syncthreads();
    if (w == 0) {
        ull s = add2(add2(swr[0][0][lane], swr[0][1][lane]),
                     add2(swr[0][2][lane], swr[0][3][lane]));
        ull q = add2(add2(swr[1][0][lane], swr[1][1][lane]),
                     add2(swr[1][2][lane], swr[1][3][lane]));
        int bid = blockIdx.z * 64 + blockIdx.y * 8 + blockIdx.x;
        g_psum[bid * 32 + lane] = s;
        g_psq[bid * 32 + lane]  = q;
    }
}

// ------------------------- BN affine finalize: reduce conv1 partials -------------------------
// grid 32 blocks (one per channel PAIR: 64 channels = 32 pairs), 256 threads
__global__ void finalize_kernel(int which, const float* __restrict__ gamma,
                                const float* __restrict__ beta) {
    __shared__ double red[256][4];
    int p = blockIdx.x;   // channel pair, 0..31
    int tid = threadIdx.x;
    double s0 = 0, s1 = 0, q0 = 0, q1 = 0;
    for (int i = tid; i < NBLK1; i += 256) {
        float2 s = unpk(g_psum[i * 32 + p]);
        float2 q = unpk(g_psq[i * 32 + p]);
        s0 += s.x; s1 += s.y; q0 += q.x; q1 += q.y;
    }
    red[tid][0] = s0; red[tid][1] = s1; red[tid][2] = q0; red[tid][3] = q1;
    __syncthreads();
    for (int st = 128; st; st >>= 1) {
        if (tid < st) {
#pragma unroll
            for (int j = 0; j < 4; j++) red[tid][j] += red[tid + st][j];
        }
        __syncthreads();
    }
    if (tid == 0) {
        float* ab = which ? g_ab2 : g_ab;
        double inv = 1.0 / (double)NVOX;
#pragma unroll
        for (int h = 0; h < 2; h++) {
            int c = 2 * p + h;     // 0..63
            double mean = red[0][h] * inv;
            double var = red[0][2 + h] * inv - mean * mean;
            float a = gamma[c] * (float)(1.0 / sqrt(var + 1e-5));
            ab[c] = a;
            ab[64 + c] = beta[c] - (float)mean * a;
        }
    }
}

// ------------------------- conv3d 64->OC, fused BN+ReLU on loads, f32x2 inner -------------------------
// EPI=0: OC=3 offset conv + meshgrid + clip + trilinear border sample -> g_samp
// EPI=1: OC=1 conv + sigmoid -> outp
// block 128 threads, tile 8x4x4 output voxels; channel-split 2x32; XOR swizzled smem.
template <int OC, int EPI>
__global__ __launch_bounds__(128) void conv2_kernel(const float* __restrict__ wg,
                                                    const float* __restrict__ bias, int which,
                                                    float* __restrict__ outp) {
    extern __shared__ float sh[];
    float* hs = sh;                    // 360 positions * 32 channels (swizzled quads)
    float* ws = sh + 11520;            // OC * 27 * 32
    float* sab = ws + OC * 864;        // 128
    const float* ab = which ? g_ab2 : g_ab;

    int tid = threadIdx.x;
    int b = blockIdx.z >> 4;
    int z0 = (blockIdx.z & 15) * 4;
    int y0 = blockIdx.y * 4, x0 = blockIdx.x * 8;
    int tx = tid & 7, ty = (tid >> 3) & 3, tz = tid >> 5;

    if (tid < 128) sab[tid] = ab[tid];

    ull acc2[OC];
#pragma unroll
    for (int oc = 0; oc < OC; oc++) acc2[oc] = 0ull;

#pragma unroll 1
    for (int p = 0; p < 2; p++) {
        __syncthreads();
        for (int i = tid; i < OC * 864; i += 128) {
            int oc = i / 864, rr = i - oc * 864, tap = rr >> 5, ic = rr & 31;
            ws[i] = wg[(oc * 64 + p * 32 + ic) * 27 + tap];
        }
        for (int i = tid; i < 2880; i += 128) {
            int c4 = i & 7, pos = i >> 3;
            int lz = pos / 60, rem = pos - lz * 60, ly = rem / 10, lx = rem - ly * 10;
            int gz = z0 + lz - 1, gy = y0 + ly - 1, gx = x0 + lx - 1;
            float4 v = make_float4(0.f, 0.f, 0.f, 0.f);
            if ((unsigned)gz < G && (unsigned)gy < G && (unsigned)gx < G) {
                float4 yv = *(const float4*)(g_y + ((size_t)(b * G3 + (gz * G + gy) * G + gx)) * 64 +
                                             p * 32 + c4 * 4);
                float4 a4 = *(const float4*)(sab + p * 32 + c4 * 4);
                float4 b4 = *(const float4*)(sab + 64 + p * 32 + c4 * 4);
                v.x = fmaxf(fmaf(a4.x, yv.x, b4.x), 0.f);
                v.y = fmaxf(fmaf(a4.y, yv.y, b4.y), 0.f);
                v.z = fmaxf(fmaf(a4.z, yv.z, b4.z), 0.f);
                v.w = fmaxf(fmaf(a4.w, yv.w, b4.w), 0.f);
            }
            *(float4*)&hs[(size_t)(pos * 8 + (c4 ^ (pos & 7))) * 4] = v;
        }
        __syncthreads();

#pragma unroll 1
        for (int dz = 0; dz < 3; dz++) {
#pragma unroll
            for (int dy = 0; dy < 3; dy++) {
#pragma unroll
                for (int dx = 0; dx < 3; dx++) {
                    int pos = ((tz + dz) * 6 + (ty + dy)) * 10 + (tx + dx);
                    int tap = (dz * 3 + dy) * 3 + dx;
                    int sw = pos & 7;
                    const float* hp = hs + pos * 32;
                    const float* wp = ws + tap * 32;
#pragma unroll
                    for (int c4 = 0; c4 < 8; c4++) {
                        ulonglong2 v2 = *(const ulonglong2*)(hp + ((c4 ^ sw) * 4));
#pragma unroll
                        for (int oc = 0; oc < OC; oc++) {
                            ulonglong2 w2 = *(const ulonglong2*)(wp + oc * 864 + c4 * 4);
                            fma2(acc2[oc], v2.x, w2.x);
                            fma2(acc2[oc], v2.y, w2.y);
                        }
                    }
                }
            }
        }
    }

    float accv[OC];
#pragma unroll
    for (int oc = 0; oc < OC; oc++) {
        float2 t = unpk(acc2[oc]);
        accv[oc] = t.x + t.y;
    }

    int d = z0 + tz, hh = y0 + ty, wxx = x0 + tx;
    int vlin = (d * G + hh) * G + wxx;

    if constexpr (EPI == 0) {
        const float step = 2.0f / 63.0f;
        float o0 = accv[0] + bias[0];
        float o1 = accv[1] + bias[1];
        float o2 = accv[2] + bias[2];
        // grid ch0 -> x (W) coord, ch1 -> y (H), ch2 -> z (D); base = (lin[d], lin[h], lin[w])
        float gxc = fminf(fmaxf(-1.0f + d * step + 0.1f * o0, -1.0f), 1.0f);
        float gyc = fminf(fmaxf(-1.0f + hh * step + 0.1f * o1, -1.0f), 1.0f);
        float gzc = fminf(fmaxf(-1.0f + wxx * step + 0.1f * o2, -1.0f), 1.0f);
        float ux = fminf(fmaxf(((gxc + 1.0f) * (float)G - 1.0f) * 0.5f, 0.0f), (float)(G - 1));
        float uy = fminf(fmaxf(((gyc + 1.0f) * (float)G - 1.0f) * 0.5f, 0.0f), (float)(G - 1));
        float uz = fminf(fmaxf(((gzc + 1.0f) * (float)G - 1.0f) * 0.5f, 0.0f), (float)(G - 1));
        float fx0 = floorf(ux), fy0 = floorf(uy), fz0 = floorf(uz);
        float fx = ux - fx0, fy = uy - fy0, fz = uz - fz0;
        int x0i = (int)fx0, y0i = (int)fy0, z0i = (int)fz0;
        int x1i = min(x0i + 1, G - 1), y1i = min(y0i + 1, G - 1), z1i = min(z0i + 1, G - 1);
        const float* vb = g_vox + b * G3;
        float v000 = vb[(z0i * G + y0i) * G + x0i];
        float v001 = vb[(z0i * G + y0i) * G + x1i];
        float v010 = vb[(z0i * G + y1i) * G + x0i];
        float v011 = vb[(z0i * G + y1i) * G + x1i];
        float v100 = vb[(z1i * G + y0i) * G + x0i];
        float v101 = vb[(z1i * G + y0i) * G + x1i];
        float v110 = vb[(z1i * G + y1i) * G + x0i];
        float v111 = vb[(z1i * G + y1i) * G + x1i];
        float wx0 = 1.0f - fx, wy0 = 1.0f - fy, wz0 = 1.0f - fz;
        float r = wz0 * (wy0 * (v000 * wx0 + v001 * fx) + fy * (v010 * wx0 + v011 * fx)) +
                  fz  * (wy0 * (v100 * wx0 + v101 * fx) + fy * (v110 * wx0 + v111 * fx));
        g_samp[b * G3 + vlin] = r;
    } else {
        float o = accv[0] + bias[0];
        outp[b * G3 + vlin] = 1.0f / (1.0f + expf(-o));
    }
}

// ------------------------- launch -------------------------
extern "C" void kernel_launch(void* const* d_in, const int* in_sizes, int n_in,
                              void* d_out, int out_size) {
    const float* points = (const float*)d_in[0];
    const float* ow1 = (const float*)d_in[1];
    const float* ob1 = (const float*)d_in[2];
    const float* ogamma = (const float*)d_in[3];
    const float* obeta = (const float*)d_in[4];
    const float* ow2 = (const float*)d_in[5];
    const float* ob2 = (const float*)d_in[6];
    const float* dw1 = (const float*)d_in[7];
    const float* db1 = (const float*)d_in[8];
    const float* dgamma = (const float*)d_in[9];
    const float* dbeta = (const float*)d_in[10];
    const float* dw2 = (const float*)d_in[11];
    const float* db2 = (const float*)d_in[12];
    float* outp = (float*)d_out;

    static bool attr_done = false;
    if (!attr_done) {
        cudaFuncSetAttribute(conv2_kernel<3, 0>, cudaFuncAttributeMaxDynamicSharedMemorySize, 57344);
        cudaFuncSetAttribute(conv2_kernel<1, 1>, cudaFuncAttributeMaxDynamicSharedMemorySize, 51200);
        attr_done = true;
    }

    init_kernel<<<2048, 256>>>();
    minmax_kernel<<<dim3(64, BATCH), 256>>>(points);
    hist_kernel<<<(BATCH * NPTS + 255) / 256, 256>>>(points);

    // branch 1: offset conv + grid sample
    conv1_kernel<<<dim3(8, 8, BATCH * 8), 128>>>(0, ow1, ob1);
    finalize_kernel<<<32, 256>>>(0, ogamma, obeta);
    conv2_kernel<3, 0><<<dim3(8, 16, BATCH * 16), 128, 56960>>>(ow2, ob2, 0, nullptr);

    // branch 2: decoder
    conv1_kernel<<<dim3(8, 8, BATCH * 8), 128>>>(1, dw1, db1);
    finalize_kernel<<<32, 256>>>(1, dgamma, dbeta);
    conv2_kernel<1, 1><<<dim3(8, 16, BATCH * 16), 128, 50048>>>(dw2, db2, 1, outp);
}